// round 15
// baseline (speedup 1.0000x reference)
#include <cuda_runtime.h>
#include <math.h>

// ---------------------------------------------------------------------------
// SelfAttention (feature attention), fp32 exact path.
//
// Per branch (inp [N=8192, M=2048], all W [2048,2048]):
//   K = inp@Kw + Kb ; Q = inp@Qw + Qb ; V = inp@Vw + Vb     (N x D)
//   att = Q^T @ K                                            (D x D)
//   w   = softmax_rows(att)        -> written directly to output
//   T   = V @ w^T                                            (N x D)
//   Y   = T @ Ow + Ob + inp        -> written directly to output
//
// Everything fp32 FFMA: softmax logits have magnitude ~30, and w is a checked
// output, so logit abs-error must be <<1e-3 -> needs fp32-class precision.
// ---------------------------------------------------------------------------

#define BM 128
#define BN 128
#define BK 16

static const int NN = 8192;
static const int DD = 2048;

// Scratch (allocation-free rule: __device__ globals)
__device__ float g_K[8192u * 2048u];
__device__ float g_Q[8192u * 2048u];
__device__ float g_V[8192u * 2048u];
__device__ float g_T[8192u * 2048u];
__device__ float g_att[2048u * 2048u];

// AMODE: 0 -> A(n,k) = A[n*lda + k]   (row-major [N,K])
//        1 -> A(n,k) = A[k*lda + n]   (transposed access, for Q^T)
// BMODE: 0 -> B(k,m) = B[k*ldb + m]   (row-major [K,M])
//        1 -> B(k,m) = B[m*ldb + k]   (transposed access, for w^T)
template <int AMODE, int BMODE, bool HAS_BIAS, bool ADD_RES>
__global__ __launch_bounds__(256, 2)
void sgemm_kernel(const float* __restrict__ A, int lda,
                  const float* __restrict__ B, int ldb,
                  const float* __restrict__ bias,
                  const float* __restrict__ res,
                  float* __restrict__ C,
                  int M, int Kdim)
{
    __shared__ float As[BK][BM];
    __shared__ float Bs[BK][BN];

    const int tid  = threadIdx.x;
    const int row0 = blockIdx.y * BM;
    const int col0 = blockIdx.x * BN;
    const int ty   = tid >> 4;   // 0..15
    const int tx   = tid & 15;   // 0..15

    float acc[8][8];
#pragma unroll
    for (int i = 0; i < 8; i++)
#pragma unroll
        for (int j = 0; j < 8; j++) acc[i][j] = 0.0f;

    for (int k0 = 0; k0 < Kdim; k0 += BK) {
        // ---- load A tile into As[k][n_local] ----
        if (AMODE == 0) {
#pragma unroll
            for (int p = 0; p < 2; p++) {
                int ar = (tid >> 2) + p * 64;        // row within tile
                int ac = (tid & 3) * 4;              // k within tile
                float4 v = *(const float4*)(A + (size_t)(row0 + ar) * lda + k0 + ac);
                As[ac + 0][ar] = v.x;
                As[ac + 1][ar] = v.y;
                As[ac + 2][ar] = v.z;
                As[ac + 3][ar] = v.w;
            }
        } else {
#pragma unroll
            for (int p = 0; p < 2; p++) {
                int ak = (tid >> 5) + p * 8;         // k within tile
                int ai = (tid & 31) * 4;             // row within tile (contiguous)
                *(float4*)&As[ak][ai] =
                    *(const float4*)(A + (size_t)(k0 + ak) * lda + row0 + ai);
            }
        }
        // ---- load B tile into Bs[k][m_local] ----
        if (BMODE == 0) {
#pragma unroll
            for (int p = 0; p < 2; p++) {
                int bk = (tid >> 5) + p * 8;
                int bm = (tid & 31) * 4;
                *(float4*)&Bs[bk][bm] =
                    *(const float4*)(B + (size_t)(k0 + bk) * ldb + col0 + bm);
            }
        } else {
#pragma unroll
            for (int p = 0; p < 2; p++) {
                int bm = (tid >> 2) + p * 64;        // m within tile
                int bk = (tid & 3) * 4;              // k within tile (contiguous)
                float4 v = *(const float4*)(B + (size_t)(col0 + bm) * ldb + k0 + bk);
                Bs[bk + 0][bm] = v.x;
                Bs[bk + 1][bm] = v.y;
                Bs[bk + 2][bm] = v.z;
                Bs[bk + 3][bm] = v.w;
            }
        }
        __syncthreads();

#pragma unroll
        for (int kk = 0; kk < BK; kk++) {
            float a[8], b[8];
            *(float4*)&a[0] = *(const float4*)&As[kk][ty * 8];
            *(float4*)&a[4] = *(const float4*)&As[kk][ty * 8 + 4];
            *(float4*)&b[0] = *(const float4*)&Bs[kk][tx * 8];
            *(float4*)&b[4] = *(const float4*)&Bs[kk][tx * 8 + 4];
#pragma unroll
            for (int i = 0; i < 8; i++)
#pragma unroll
                for (int j = 0; j < 8; j++)
                    acc[i][j] = fmaf(a[i], b[j], acc[i][j]);
        }
        __syncthreads();
    }

    // ---- epilogue: bias + residual + store ----
#pragma unroll
    for (int i = 0; i < 8; i++) {
        const int r = row0 + ty * 8 + i;
#pragma unroll
        for (int j = 0; j < 8; j += 4) {
            const int c = col0 + tx * 8 + j;
            float4 o;
            o.x = acc[i][j + 0];
            o.y = acc[i][j + 1];
            o.z = acc[i][j + 2];
            o.w = acc[i][j + 3];
            if (HAS_BIAS) {
                float4 bv = *(const float4*)(bias + c);
                o.x += bv.x; o.y += bv.y; o.z += bv.z; o.w += bv.w;
            }
            if (ADD_RES) {
                float4 rv = *(const float4*)(res + (size_t)r * M + c);
                o.x += rv.x; o.y += rv.y; o.z += rv.z; o.w += rv.w;
            }
            *(float4*)(C + (size_t)r * M + c) = o;
        }
    }
}

// Row softmax: one block per row (D = 2048), 256 threads.
__global__ __launch_bounds__(256)
void softmax_rows_kernel(const float* __restrict__ A, float* __restrict__ W, int D)
{
    const int row = blockIdx.x;
    const float* a = A + (size_t)row * D;
    float* w = W + (size_t)row * D;
    __shared__ float red[256];
    const int tid = threadIdx.x;

    float m = -INFINITY;
    for (int j = tid; j < D; j += 256) m = fmaxf(m, a[j]);
    red[tid] = m;
    __syncthreads();
    for (int s = 128; s > 0; s >>= 1) {
        if (tid < s) red[tid] = fmaxf(red[tid], red[tid + s]);
        __syncthreads();
    }
    m = red[0];
    __syncthreads();

    float sum = 0.0f;
    for (int j = tid; j < D; j += 256) {
        float e = expf(a[j] - m);
        w[j] = e;
        sum += e;
    }
    red[tid] = sum;
    __syncthreads();
    for (int s = 128; s > 0; s >>= 1) {
        if (tid < s) red[tid] += red[tid + s];
        __syncthreads();
    }
    const float inv = 1.0f / red[0];
    for (int j = tid; j < D; j += 256) w[j] *= inv;
}

static void run_branch(const float* inp,
                       const float* Kw, const float* Kb,
                       const float* Qw, const float* Qb,
                       const float* Vw, const float* Vb,
                       const float* Ow, const float* Ob,
                       float* outY, float* outW,
                       float* bK, float* bQ, float* bV, float* bAtt, float* bT)
{
    dim3 blk(256);
    dim3 gP(DD / BN, NN / BM);   // 16 x 64 : [8192 x 2048] outputs
    dim3 gA(DD / BN, DD / BM);   // 16 x 16 : [2048 x 2048] output

    // K, Q, V projections (NN, +bias)
    sgemm_kernel<0, 0, true, false><<<gP, blk>>>(inp, DD, Kw, DD, Kb, nullptr, bK, DD, DD);
    sgemm_kernel<0, 0, true, false><<<gP, blk>>>(inp, DD, Qw, DD, Qb, nullptr, bQ, DD, DD);
    sgemm_kernel<0, 0, true, false><<<gP, blk>>>(inp, DD, Vw, DD, Vb, nullptr, bV, DD, DD);

    // att = Q^T @ K  (TN over n=8192)
    sgemm_kernel<1, 0, false, false><<<gA, blk>>>(bQ, DD, bK, DD, nullptr, nullptr, bAtt, DD, NN);

    // w = softmax(att) rows -> directly into output
    softmax_rows_kernel<<<DD, blk>>>(bAtt, outW, DD);

    // T = V @ w^T  (NT)
    sgemm_kernel<0, 1, false, false><<<gP, blk>>>(bV, DD, outW, DD, nullptr, nullptr, bT, DD, DD);

    // Y = T @ Ow + Ob + inp  (NN, +bias, +residual) -> directly into output
    sgemm_kernel<0, 0, true, true><<<gP, blk>>>(bT, DD, Ow, DD, Ob, inp, outY, DD, DD);
}

extern "C" void kernel_launch(void* const* d_in, const int* in_sizes, int n_in,
                              void* d_out, int out_size)
{
    const float* x    = (const float*)d_in[0];
    const float* y    = (const float*)d_in[1];
    const float* QK_w = (const float*)d_in[2];
    const float* QK_b = (const float*)d_in[3];
    const float* QQ_w = (const float*)d_in[4];
    const float* QQ_b = (const float*)d_in[5];
    const float* QV_w = (const float*)d_in[6];
    const float* QV_b = (const float*)d_in[7];
    const float* QO_w = (const float*)d_in[8];
    const float* QO_b = (const float*)d_in[9];
    const float* FK_w = (const float*)d_in[10];
    const float* FK_b = (const float*)d_in[11];
    const float* FQ_w = (const float*)d_in[12];
    const float* FQ_b = (const float*)d_in[13];
    const float* FV_w = (const float*)d_in[14];
    const float* FV_b = (const float*)d_in[15];
    const float* FO_w = (const float*)d_in[16];
    const float* FO_b = (const float*)d_in[17];

    float* out = (float*)d_out;
    const size_t SZ_Y = (size_t)NN * DD;   // 16,777,216
    const size_t SZ_W = (size_t)DD * DD;   //  4,194,304
    float* outQy   = out;
    float* outQatt = out + SZ_Y;
    float* outFy   = out + SZ_Y + SZ_W;
    float* outFatt = out + 2 * SZ_Y + SZ_W;

    float *pK, *pQ, *pV, *pAtt, *pT;
    cudaGetSymbolAddress((void**)&pK,   g_K);
    cudaGetSymbolAddress((void**)&pQ,   g_Q);
    cudaGetSymbolAddress((void**)&pV,   g_V);
    cudaGetSymbolAddress((void**)&pAtt, g_att);
    cudaGetSymbolAddress((void**)&pT,   g_T);

    run_branch(x, QK_w, QK_b, QQ_w, QQ_b, QV_w, QV_b, QO_w, QO_b,
               outQy, outQatt, pK, pQ, pV, pAtt, pT);
    run_branch(y, FK_w, FK_b, FQ_w, FQ_b, FV_w, FV_b, FO_w, FO_b,
               outFy, outFatt, pK, pQ, pV, pAtt, pT);
}

// round 17
// speedup vs baseline: 2.3422x; 2.3422x over previous
#include <cuda_runtime.h>
#include <cstdint>
#include <math.h>

// ---------------------------------------------------------------------------
// SelfAttention via mma.sync tf32 (3x-split where precision requires), sm_103
// baseline PTX (tcgen05 unavailable: harness PTX target is sm_103, not 103a).
//
// Canonical GEMM form D[m][n] = sum_k A[m][k]*B[n][k], both K-major.
// Split GEMMs (K proj, Q proj, att): operands as tf32 hi/lo planes, 3 MMAs.
// Single GEMMs (V, T, Y): hi plane only.
// ---------------------------------------------------------------------------

#define BM 128
#define BN 128
#define BK 32
#define STAGES 3

static const int NSAMP = 8192;
static const int DFEAT = 2048;

// ------------------------- device scratch (no allocs) ----------------------
__device__ float g_inp_hi[8192u * 2048u];
__device__ float g_inp_lo[8192u * 2048u];
__device__ float g_wK_hi[2048u * 2048u];
__device__ float g_wK_lo[2048u * 2048u];
__device__ float g_wQ_hi[2048u * 2048u];
__device__ float g_wQ_lo[2048u * 2048u];
__device__ float g_wV_hi[2048u * 2048u];
__device__ float g_wO_hi[2048u * 2048u];
__device__ float g_Kt_hi[2048u * 8192u];
__device__ float g_Kt_lo[2048u * 8192u];
__device__ float g_Qt_hi[2048u * 8192u];
__device__ float g_Qt_lo[2048u * 8192u];
__device__ float g_V_hi[8192u * 2048u];
__device__ float g_T_hi[8192u * 2048u];
__device__ float g_att[2048u * 2048u];
__device__ float g_w_hi[2048u * 2048u];

// ------------------------------ PTX helpers --------------------------------
__device__ __forceinline__ uint32_t smem_u32(const void* p) {
    uint32_t a;
    asm("{ .reg .u64 t; cvta.to.shared.u64 t, %1; cvt.u32.u64 %0, t; }"
        : "=r"(a) : "l"(p));
    return a;
}

__device__ __forceinline__ void cp16(uint32_t s, const void* g) {
    asm volatile("cp.async.cg.shared.global [%0], [%1], 16;\n"
                 :: "r"(s), "l"(g));
}

#define CP_COMMIT() asm volatile("cp.async.commit_group;\n" ::: "memory")
#define CP_WAIT2()  asm volatile("cp.async.wait_group 2;\n" ::: "memory")

__device__ __forceinline__ void ldsm4(uint32_t* r, uint32_t addr) {
    asm volatile("ldmatrix.sync.aligned.m8n8.x4.shared.b16 {%0,%1,%2,%3}, [%4];\n"
                 : "=r"(r[0]), "=r"(r[1]), "=r"(r[2]), "=r"(r[3]) : "r"(addr));
}

__device__ __forceinline__ void mma8(float* c, const uint32_t* a, const uint32_t* b) {
    asm volatile(
        "mma.sync.aligned.m16n8k8.row.col.f32.tf32.tf32.f32 "
        "{%0,%1,%2,%3}, {%4,%5,%6,%7}, {%8,%9}, {%0,%1,%2,%3};\n"
        : "+f"(c[0]), "+f"(c[1]), "+f"(c[2]), "+f"(c[3])
        : "r"(a[0]), "r"(a[1]), "r"(a[2]), "r"(a[3]), "r"(b[0]), "r"(b[1]));
}

__device__ __forceinline__ float tf32_rna(float x) {
    uint32_t u;
    asm("cvt.rna.tf32.f32 %0, %1;" : "=r"(u) : "f"(x));
    return __uint_as_float(u);
}

// Load one pipeline stage: A/B (and lo planes if SPLIT) BMxBK / BNxBK tf32.
// lso: precomputed swizzled (row,chunk) offset for this thread (rows 0..31).
template <bool SPLIT>
__device__ __forceinline__ void stage_load(
    uint32_t s, const float* gA, const float* gB,
    const float* gAl, const float* gBl, size_t strideElems, uint32_t lso)
{
    const int PLANE = BM * BK * 4;  // 16384 bytes
#pragma unroll
    for (int p = 0; p < 4; p++) {
        const size_t go = strideElems * (size_t)(p * 32);
        cp16(s + lso + p * 4096, gA + go);
        cp16(s + PLANE + lso + p * 4096, gB + go);
        if (SPLIT) {
            cp16(s + 2 * PLANE + lso + p * 4096, gAl + go);
            cp16(s + 3 * PLANE + lso + p * 4096, gBl + go);
        }
    }
}

// ------------------------------ GEMM kernel --------------------------------
// BIAS_MODE: 0 none, 1 per-row (bias[m]), 2 per-col (bias[n])
// OUT_MODE : 0 fp32 C, 1 tf32 hi plane only, 2 hi+lo planes
template <bool SPLIT, int BIAS_MODE, bool ADD_RES, int OUT_MODE>
__global__ void __launch_bounds__(256)
mma_gemm(const float* __restrict__ Ah, const float* __restrict__ Al,
         const float* __restrict__ Bh, const float* __restrict__ Bl,
         const float* __restrict__ bias, const float* __restrict__ res,
         float* __restrict__ C, float* __restrict__ Ch, float* __restrict__ Cl,
         int Kdim, int Ntot)
{
    extern __shared__ char smem[];
    const uint32_t sbase = smem_u32(smem);
    const int tid  = threadIdx.x;
    const int wid  = tid >> 5;
    const int lane = tid & 31;
    const int wm = wid & 1;        // 2 warps over M (64 rows each)
    const int wn = wid >> 1;       // 4 warps over N (32 cols each)
    const int m0 = blockIdx.y * BM;
    const int n0 = blockIdx.x * BN;

    const int PLANE = BM * BK * 4;                    // 16 KB
    const int STAGE = (SPLIT ? 4 : 2) * PLANE;        // 64 / 32 KB

    // ---- loader thread mapping: 16B chunk (row = tid/8, kc = tid%8) ----
    const int lrow = tid >> 3;                        // 0..31
    const int lkc  = tid & 7;
    const uint32_t lso = (uint32_t)(lrow * 128 + ((lkc * 16) ^ ((lrow & 7) * 16)));

    const float* gA0  = Ah + (size_t)(m0 + lrow) * Kdim + lkc * 4;
    const float* gB0  = Bh + (size_t)(n0 + lrow) * Kdim + lkc * 4;
    const float* gA0l = SPLIT ? (Al + (size_t)(m0 + lrow) * Kdim + lkc * 4) : nullptr;
    const float* gB0l = SPLIT ? (Bl + (size_t)(n0 + lrow) * Kdim + lkc * 4) : nullptr;

    // ---- ldmatrix fragment address components ----
    const uint32_t xorv = (uint32_t)((lane & 7) * 16);
    // A: matrices 0..3 = (rows 0-7,k-lo),(rows 8-15,k-lo),(rows 0-7,k-hi),(rows 8-15,k-hi)
    const int amrow = wm * 64 + ((lane >> 3) & 1) * 8 + (lane & 7);
    const uint32_t a_kb = ((lane >> 4) & 1) * 16;
    uint32_t aoff[4], akp[4];
#pragma unroll
    for (int i = 0; i < 4; i++) aoff[i] = (uint32_t)((amrow + i * 16) * 128);
#pragma unroll
    for (int ks = 0; ks < 4; ks++) akp[ks] = (uint32_t)((ks * 32 + a_kb)) ^ xorv;
    // B: matrices = (ntile j,k-lo),(ntile j,k-hi),(ntile j+1,k-lo),(ntile j+1,k-hi)
    const int bnrow = wn * 32 + ((lane >> 4) & 1) * 8 + (lane & 7);
    const uint32_t b_kb = ((lane >> 3) & 1) * 16;
    uint32_t boff[2], bkp[4];
#pragma unroll
    for (int jp = 0; jp < 2; jp++) boff[jp] = (uint32_t)((bnrow + jp * 16) * 128);
#pragma unroll
    for (int ks = 0; ks < 4; ks++) bkp[ks] = (uint32_t)((ks * 32 + b_kb)) ^ xorv;

    float acc[4][4][4];
#pragma unroll
    for (int i = 0; i < 4; i++)
#pragma unroll
        for (int j = 0; j < 4; j++)
#pragma unroll
            for (int q = 0; q < 4; q++) acc[i][j][q] = 0.0f;

    const int NC = Kdim / BK;

    // ---- prologue: fill pipeline ----
#pragma unroll
    for (int s = 0; s < STAGES; s++) {
        stage_load<SPLIT>(sbase + s * STAGE, gA0 + s * BK, gB0 + s * BK,
                          gA0l + (SPLIT ? s * BK : 0), gB0l + (SPLIT ? s * BK : 0),
                          (size_t)Kdim, lso);
        CP_COMMIT();
    }

    int buf = 0;
    for (int c = 0; c < NC; c++) {
        CP_WAIT2();
        __syncthreads();
        const uint32_t sA = sbase + buf * STAGE;
        const uint32_t sB = sA + PLANE;

#pragma unroll
        for (int ks = 0; ks < 4; ks++) {
            uint32_t ah[4][4], bh[4][2];
#pragma unroll
            for (int i = 0; i < 4; i++) ldsm4(ah[i], sA + aoff[i] + akp[ks]);
#pragma unroll
            for (int jp = 0; jp < 2; jp++) {
                uint32_t r[4];
                ldsm4(r, sB + boff[jp] + bkp[ks]);
                bh[jp * 2][0] = r[0]; bh[jp * 2][1] = r[1];
                bh[jp * 2 + 1][0] = r[2]; bh[jp * 2 + 1][1] = r[3];
            }
            if (SPLIT) {
                uint32_t al[4][4], bl[4][2];
                const uint32_t sAl = sA + 2 * PLANE;
                const uint32_t sBl = sA + 3 * PLANE;
#pragma unroll
                for (int i = 0; i < 4; i++) ldsm4(al[i], sAl + aoff[i] + akp[ks]);
#pragma unroll
                for (int jp = 0; jp < 2; jp++) {
                    uint32_t r[4];
                    ldsm4(r, sBl + boff[jp] + bkp[ks]);
                    bl[jp * 2][0] = r[0]; bl[jp * 2][1] = r[1];
                    bl[jp * 2 + 1][0] = r[2]; bl[jp * 2 + 1][1] = r[3];
                }
                // hi*hi
#pragma unroll
                for (int i = 0; i < 4; i++)
#pragma unroll
                    for (int j = 0; j < 4; j++) mma8(acc[i][j], ah[i], bh[j]);
                // hi*lo
#pragma unroll
                for (int i = 0; i < 4; i++)
#pragma unroll
                    for (int j = 0; j < 4; j++) mma8(acc[i][j], ah[i], bl[j]);
                // lo*hi
#pragma unroll
                for (int i = 0; i < 4; i++)
#pragma unroll
                    for (int j = 0; j < 4; j++) mma8(acc[i][j], al[i], bh[j]);
            } else {
#pragma unroll
                for (int i = 0; i < 4; i++)
#pragma unroll
                    for (int j = 0; j < 4; j++) mma8(acc[i][j], ah[i], bh[j]);
            }
        }
        __syncthreads();
        const int cn = c + STAGES;
        if (cn < NC) {
            stage_load<SPLIT>(sbase + buf * STAGE, gA0 + cn * BK, gB0 + cn * BK,
                              gA0l + (SPLIT ? cn * BK : 0),
                              gB0l + (SPLIT ? cn * BK : 0),
                              (size_t)Kdim, lso);
        }
        CP_COMMIT();
        buf = (buf + 1 == STAGES) ? 0 : buf + 1;
    }

    // ---- epilogue ----
    const int er = m0 + wm * 64 + (lane >> 2);
    const int ec = n0 + wn * 32 + (lane & 3) * 2;
#pragma unroll
    for (int i = 0; i < 4; i++) {
        const int r0 = er + i * 16;
        const int r1 = r0 + 8;
        float br0 = 0.0f, br1 = 0.0f;
        if (BIAS_MODE == 1) { br0 = bias[r0]; br1 = bias[r1]; }
#pragma unroll
        for (int j = 0; j < 4; j++) {
            const int c0 = ec + j * 8;
            float v00 = acc[i][j][0], v01 = acc[i][j][1];
            float v10 = acc[i][j][2], v11 = acc[i][j][3];
            if (BIAS_MODE == 1) { v00 += br0; v01 += br0; v10 += br1; v11 += br1; }
            if (BIAS_MODE == 2) {
                const float bb0 = bias[c0], bb1 = bias[c0 + 1];
                v00 += bb0; v01 += bb1; v10 += bb0; v11 += bb1;
            }
            if (ADD_RES) {
                float2 ra = *(const float2*)(res + (size_t)r0 * Ntot + c0);
                float2 rb = *(const float2*)(res + (size_t)r1 * Ntot + c0);
                v00 += ra.x; v01 += ra.y; v10 += rb.x; v11 += rb.y;
            }
            if (OUT_MODE == 0) {
                *(float2*)(C + (size_t)r0 * Ntot + c0) = make_float2(v00, v01);
                *(float2*)(C + (size_t)r1 * Ntot + c0) = make_float2(v10, v11);
            } else {
                const float h00 = tf32_rna(v00), h01 = tf32_rna(v01);
                const float h10 = tf32_rna(v10), h11 = tf32_rna(v11);
                *(float2*)(Ch + (size_t)r0 * Ntot + c0) = make_float2(h00, h01);
                *(float2*)(Ch + (size_t)r1 * Ntot + c0) = make_float2(h10, h11);
                if (OUT_MODE == 2) {
                    *(float2*)(Cl + (size_t)r0 * Ntot + c0) =
                        make_float2(tf32_rna(v00 - h00), tf32_rna(v01 - h01));
                    *(float2*)(Cl + (size_t)r1 * Ntot + c0) =
                        make_float2(tf32_rna(v10 - h10), tf32_rna(v11 - h11));
                }
            }
        }
    }
}

// ------------------------- split / transpose kernels -----------------------
__global__ void __launch_bounds__(256)
split_kernel(const float4* __restrict__ x, float4* __restrict__ h,
             float4* __restrict__ l, int n4)
{
    for (int i = blockIdx.x * blockDim.x + threadIdx.x; i < n4;
         i += gridDim.x * blockDim.x) {
        const float4 v = x[i];
        float4 hh, ll;
        hh.x = tf32_rna(v.x); ll.x = tf32_rna(v.x - hh.x);
        hh.y = tf32_rna(v.y); ll.y = tf32_rna(v.y - hh.y);
        hh.z = tf32_rna(v.z); ll.z = tf32_rna(v.z - hh.z);
        hh.w = tf32_rna(v.w); ll.w = tf32_rna(v.w - hh.w);
        h[i] = hh; l[i] = ll;
    }
}

template <bool WRITE_LO>
__global__ void __launch_bounds__(256)
transpose_split_kernel(const float* __restrict__ W, float* __restrict__ Th,
                       float* __restrict__ Tl)
{
    __shared__ float t[32][33];
    const int bx = blockIdx.x * 32;
    const int by = blockIdx.y * 32;
    const int tx = threadIdx.x, ty = threadIdx.y;
#pragma unroll
    for (int j = 0; j < 32; j += 8)
        t[ty + j][tx] = W[(size_t)(by + ty + j) * 2048 + bx + tx];
    __syncthreads();
#pragma unroll
    for (int j = 0; j < 32; j += 8) {
        const float v = t[tx][ty + j];
        const float h = tf32_rna(v);
        const size_t o = (size_t)(bx + ty + j) * 2048 + by + tx;
        Th[o] = h;
        if (WRITE_LO) Tl[o] = tf32_rna(v - h);
    }
}

// Row softmax -> fp32 output + tf32 hi plane
__global__ void __launch_bounds__(256)
softmax_rows_kernel(const float* __restrict__ A, float* __restrict__ W,
                    float* __restrict__ Wh, int D)
{
    const int row = blockIdx.x;
    const float* a = A + (size_t)row * D;
    float* w  = W  + (size_t)row * D;
    float* wh = Wh + (size_t)row * D;
    __shared__ float red[256];
    const int tid = threadIdx.x;

    float m = -INFINITY;
    for (int j = tid; j < D; j += 256) m = fmaxf(m, a[j]);
    red[tid] = m;
    __syncthreads();
    for (int s = 128; s > 0; s >>= 1) {
        if (tid < s) red[tid] = fmaxf(red[tid], red[tid + s]);
        __syncthreads();
    }
    m = red[0];
    __syncthreads();

    float sum = 0.0f;
    for (int j = tid; j < D; j += 256) {
        const float e = expf(a[j] - m);
        w[j] = e;
        sum += e;
    }
    red[tid] = sum;
    __syncthreads();
    for (int s = 128; s > 0; s >>= 1) {
        if (tid < s) red[tid] += red[tid + s];
        __syncthreads();
    }
    const float inv = 1.0f / red[0];
    for (int j = tid; j < D; j += 256) {
        const float val = w[j] * inv;
        w[j] = val;
        wh[j] = tf32_rna(val);
    }
}

// ------------------------------- host side ---------------------------------
template <bool SPLIT, int BIAS_MODE, bool ADD_RES, int OUT_MODE>
static void launch_gemm(int Mtot, int Ntot, int Kdim,
                        const float* Ah, const float* Al,
                        const float* Bh, const float* Bl,
                        const float* bias, const float* res,
                        float* C, float* Ch, float* Cl)
{
    const int smem = (SPLIT ? 4 : 2) * BM * BK * 4 * STAGES;
    cudaFuncSetAttribute(mma_gemm<SPLIT, BIAS_MODE, ADD_RES, OUT_MODE>,
                         cudaFuncAttributeMaxDynamicSharedMemorySize, smem);
    dim3 g(Ntot / BN, Mtot / BM);
    mma_gemm<SPLIT, BIAS_MODE, ADD_RES, OUT_MODE><<<g, 256, smem>>>(
        Ah, Al, Bh, Bl, bias, res, C, Ch, Cl, Kdim, Ntot);
}

struct Scratch {
    float *inp_hi, *inp_lo;
    float *wK_hi, *wK_lo, *wQ_hi, *wQ_lo, *wV_hi, *wO_hi;
    float *Kt_hi, *Kt_lo, *Qt_hi, *Qt_lo;
    float *V_hi, *T_hi, *att, *w_hi;
};

static void run_branch(const float* inp,
                       const float* Kw, const float* Kb,
                       const float* Qw, const float* Qb,
                       const float* Vw, const float* Vb,
                       const float* Ow, const float* Ob,
                       float* outY, float* outW, const Scratch& P)
{
    split_kernel<<<2048, 256>>>((const float4*)inp, (float4*)P.inp_hi,
                                (float4*)P.inp_lo, NSAMP * DFEAT / 4);
    dim3 tg(DFEAT / 32, DFEAT / 32), tb(32, 8);
    transpose_split_kernel<true ><<<tg, tb>>>(Kw, P.wK_hi, P.wK_lo);
    transpose_split_kernel<true ><<<tg, tb>>>(Qw, P.wQ_hi, P.wQ_lo);
    transpose_split_kernel<false><<<tg, tb>>>(Vw, P.wV_hi, nullptr);
    transpose_split_kernel<false><<<tg, tb>>>(Ow, P.wO_hi, nullptr);

    // Kt = (inp@Kw + Kb)^T : A=Kw^T [d][k], B=inp [n][k]; bias per-row -> planes
    launch_gemm<true, 1, false, 2>(DFEAT, NSAMP, DFEAT, P.wK_hi, P.wK_lo,
                                   P.inp_hi, P.inp_lo, Kb, nullptr,
                                   nullptr, P.Kt_hi, P.Kt_lo);
    launch_gemm<true, 1, false, 2>(DFEAT, NSAMP, DFEAT, P.wQ_hi, P.wQ_lo,
                                   P.inp_hi, P.inp_lo, Qb, nullptr,
                                   nullptr, P.Qt_hi, P.Qt_lo);
    // V = inp@Vw + Vb : single tf32, hi-plane output
    launch_gemm<false, 2, false, 1>(NSAMP, DFEAT, DFEAT, P.inp_hi, nullptr,
                                    P.wV_hi, nullptr, Vb, nullptr,
                                    nullptr, P.V_hi, nullptr);
    // att[i][j] = sum_n Qt[i][n]*Kt[j][n] : split, fp32 out
    launch_gemm<true, 0, false, 0>(DFEAT, DFEAT, NSAMP, P.Qt_hi, P.Qt_lo,
                                   P.Kt_hi, P.Kt_lo, nullptr, nullptr,
                                   P.att, nullptr, nullptr);
    softmax_rows_kernel<<<DFEAT, 256>>>(P.att, outW, P.w_hi, DFEAT);
    // T = V @ w^T : single
    launch_gemm<false, 0, false, 1>(NSAMP, DFEAT, DFEAT, P.V_hi, nullptr,
                                    P.w_hi, nullptr, nullptr, nullptr,
                                    nullptr, P.T_hi, nullptr);
    // Y = T @ Ow + Ob + inp : single, fp32 out
    launch_gemm<false, 2, true, 0>(NSAMP, DFEAT, DFEAT, P.T_hi, nullptr,
                                   P.wO_hi, nullptr, Ob, inp,
                                   outY, nullptr, nullptr);
}

extern "C" void kernel_launch(void* const* d_in, const int* in_sizes, int n_in,
                              void* d_out, int out_size)
{
    const float* x    = (const float*)d_in[0];
    const float* y    = (const float*)d_in[1];
    const float* QK_w = (const float*)d_in[2];
    const float* QK_b = (const float*)d_in[3];
    const float* QQ_w = (const float*)d_in[4];
    const float* QQ_b = (const float*)d_in[5];
    const float* QV_w = (const float*)d_in[6];
    const float* QV_b = (const float*)d_in[7];
    const float* QO_w = (const float*)d_in[8];
    const float* QO_b = (const float*)d_in[9];
    const float* FK_w = (const float*)d_in[10];
    const float* FK_b = (const float*)d_in[11];
    const float* FQ_w = (const float*)d_in[12];
    const float* FQ_b = (const float*)d_in[13];
    const float* FV_w = (const float*)d_in[14];
    const float* FV_b = (const float*)d_in[15];
    const float* FO_w = (const float*)d_in[16];
    const float* FO_b = (const float*)d_in[17];

    float* out = (float*)d_out;
    const size_t SZ_Y = (size_t)NSAMP * DFEAT;
    const size_t SZ_W = (size_t)DFEAT * DFEAT;
    float* outQy   = out;
    float* outQatt = out + SZ_Y;
    float* outFy   = out + SZ_Y + SZ_W;
    float* outFatt = out + 2 * SZ_Y + SZ_W;

    Scratch P;
    cudaGetSymbolAddress((void**)&P.inp_hi, g_inp_hi);
    cudaGetSymbolAddress((void**)&P.inp_lo, g_inp_lo);
    cudaGetSymbolAddress((void**)&P.wK_hi, g_wK_hi);
    cudaGetSymbolAddress((void**)&P.wK_lo, g_wK_lo);
    cudaGetSymbolAddress((void**)&P.wQ_hi, g_wQ_hi);
    cudaGetSymbolAddress((void**)&P.wQ_lo, g_wQ_lo);
    cudaGetSymbolAddress((void**)&P.wV_hi, g_wV_hi);
    cudaGetSymbolAddress((void**)&P.wO_hi, g_wO_hi);
    cudaGetSymbolAddress((void**)&P.Kt_hi, g_Kt_hi);
    cudaGetSymbolAddress((void**)&P.Kt_lo, g_Kt_lo);
    cudaGetSymbolAddress((void**)&P.Qt_hi, g_Qt_hi);
    cudaGetSymbolAddress((void**)&P.Qt_lo, g_Qt_lo);
    cudaGetSymbolAddress((void**)&P.V_hi,  g_V_hi);
    cudaGetSymbolAddress((void**)&P.T_hi,  g_T_hi);
    cudaGetSymbolAddress((void**)&P.att,   g_att);
    cudaGetSymbolAddress((void**)&P.w_hi,  g_w_hi);

    run_branch(x, QK_w, QK_b, QQ_w, QQ_b, QV_w, QV_b, QO_w, QO_b,
               outQy, outQatt, P);
    run_branch(y, FK_w, FK_b, FQ_w, FQ_b, FV_w, FV_b, FO_w, FO_b,
               outFy, outFatt, P);
}